// round 7
// baseline (speedup 1.0000x reference)
#include <cuda_runtime.h>
#include <math.h>
#include <stdint.h>

#define Bn   8
#define HWn  1024
#define NEGn 256

// ---------------- device scratch ----------------------------------------------
__device__ float g_z1sq[Bn * HWn];
__device__ __align__(16) unsigned short g_gc[(size_t)Bn * HWn * HWn]; // 16MB cos table (bf16)
__device__ float g_pn [Bn * 16 * NEGn];
__device__ float g_s0p[Bn * 16];
__device__ unsigned g_ticket = 0;

__device__ __forceinline__ uint32_t smem_to_u32(const void* p) {
    uint32_t a;
    asm("{ .reg .u64 t; cvta.to.shared.u64 t, %1; cvt.u32.u64 %0, t; }" : "=r"(a) : "l"(p));
    return a;
}
#define SMEM_SWIZZLE_128B(o) ((o) ^ (((o) >> 3) & 0x70))

// round-to-nearest-even fp32 -> bf16-valued fp32
__device__ __forceinline__ float bf16q(float f) {
    unsigned u = __float_as_uint(f);
    u = (u + 0x7FFFu + ((u >> 16) & 1u)) & 0xFFFF0000u;
    return __uint_as_float(u);
}

__device__ __forceinline__ void ldsm_x4(uint32_t& r0, uint32_t& r1, uint32_t& r2,
                                        uint32_t& r3, uint32_t addr) {
    asm volatile("ldmatrix.sync.aligned.m8n8.x4.shared.b16 {%0,%1,%2,%3}, [%4];"
                 : "=r"(r0), "=r"(r1), "=r"(r2), "=r"(r3) : "r"(addr));
}
__device__ __forceinline__ void ldsm_x2(uint32_t& r0, uint32_t& r1, uint32_t addr) {
    asm volatile("ldmatrix.sync.aligned.m8n8.x2.shared.b16 {%0,%1}, [%2];"
                 : "=r"(r0), "=r"(r1) : "r"(addr));
}
__device__ __forceinline__ void mma16816(float* c, const uint32_t* a, const uint32_t* b) {
    asm volatile("mma.sync.aligned.m16n8k16.row.col.f32.bf16.bf16.f32 "
                 "{%0,%1,%2,%3}, {%4,%5,%6,%7}, {%8,%9}, {%0,%1,%2,%3};"
                 : "+f"(c[0]), "+f"(c[1]), "+f"(c[2]), "+f"(c[3])
                 : "r"(a[0]), "r"(a[1]), "r"(a[2]), "r"(a[3]), "r"(b[0]), "r"(b[1]));
}

// ---------------- GEMM (with fused prep): G[b][p][q] = cos(z1_p, z2_q) bf16 ----
// grid (8 qtile, 8 ptile, 8 b), 256 threads (8 warps, 2x4 warp grid)
#define SM_AS    0
#define SM_BS    16384
#define SM_TS    32768                      // fp32 staging 64 x 132 (33792B)
#define TS_PITCH 132
#define SM_STG   32768                      // output staging overlays TS
#define STG_WPR  68                         // words per stage row (64 + 4 pad)
#define SM_RZ1   (SM_STG + 128 * STG_WPR * 4)   // 67584
#define SM_RZ2   (SM_RZ1 + 512)
#define SM_GEMM_TOTAL (SM_RZ2 + 512)        // 68608

__global__ void __launch_bounds__(256) gemm_kernel(const float* __restrict__ z1,
                                                   const float* __restrict__ z2) {
    extern __shared__ char smem[];
    const uint32_t sb = smem_to_u32(smem);
    const int t = threadIdx.x, w = t >> 5, lane = t & 31;
    const int qtile = blockIdx.x, ptile = blockIdx.y, b = blockIdx.z;
    const int wm = w >> 2, wn = w & 3;          // warp tile: 64 p x 32 q

    float* ts = (float*)(smem + SM_TS);

    // ---- fused prep: stage fp32 tile, quantize, norms, pack swizzled bf16 ----
    #pragma unroll
    for (int side = 0; side < 2; side++) {
        const float* src  = side ? (z2 + ((b * 64) << 10) + (qtile << 7))
                                 : (z1 + ((b * 64) << 10) + (ptile << 7));
        float* rzs = (float*)(smem + (side ? SM_RZ2 : SM_RZ1));
        const int dsttile = side ? SM_BS : SM_AS;

        #pragma unroll
        for (int it = 0; it < 8; it++) {
            int u = it * 256 + t;
            int c = u >> 5, jq = u & 31;
            float4 v = *(const float4*)(src + (c << 10) + jq * 4);
            float* d = ts + c * TS_PITCH + jq * 4;
            d[0] = bf16q(v.x); d[1] = bf16q(v.y);
            d[2] = bf16q(v.z); d[3] = bf16q(v.w);
        }
        __syncthreads();

        if (t < 128) {          // per-pixel norms (conflict-free column reads)
            float s = 0.f;
            #pragma unroll
            for (int c = 0; c < 64; c++) {
                float x = ts[c * TS_PITCH + t];
                s += x * x;
            }
            rzs[t] = rsqrtf(s);
            if (side == 0 && qtile == 0)
                g_z1sq[(b << 10) + (ptile << 7) + t] = s;
        }

        // pack to swizzled bf16 tile: 128 rows x 32 words
        #pragma unroll
        for (int it = 0; it < 16; it++) {
            int u = it * 256 + t;
            int p = u & 127, cp = u >> 7;
            unsigned lo = __float_as_uint(ts[(2 * cp)     * TS_PITCH + p]) >> 16;
            unsigned hi = __float_as_uint(ts[(2 * cp + 1) * TS_PITCH + p]) >> 16;
            *(uint32_t*)(smem + dsttile +
                         SMEM_SWIZZLE_128B((uint32_t)(p * 128 + cp * 4))) = lo | (hi << 16);
        }
        __syncthreads();
    }

    // ---- MMA mainloop ----
    float c[4][4][4];
    #pragma unroll
    for (int mi = 0; mi < 4; mi++)
        #pragma unroll
        for (int ni = 0; ni < 4; ni++)
            #pragma unroll
            for (int r = 0; r < 4; r++) c[mi][ni][r] = 0.f;

    #pragma unroll
    for (int ks = 0; ks < 4; ks++) {
        uint32_t a[4][4], bb[4][2];
        #pragma unroll
        for (int mi = 0; mi < 4; mi++) {
            int row  = (wm << 6) + (mi << 4) + (lane & 15);
            int half = lane >> 4;
            uint32_t off = SMEM_SWIZZLE_128B((uint32_t)(row * 128 + ks * 32 + half * 16));
            ldsm_x4(a[mi][0], a[mi][1], a[mi][2], a[mi][3], sb + SM_AS + off);
        }
        #pragma unroll
        for (int ni = 0; ni < 4; ni++) {
            int row  = (wn << 5) + (ni << 3) + (lane & 7);
            int half = (lane >> 3) & 1;
            uint32_t off = SMEM_SWIZZLE_128B((uint32_t)(row * 128 + ks * 32 + half * 16));
            ldsm_x2(bb[ni][0], bb[ni][1], sb + SM_BS + off);
        }
        #pragma unroll
        for (int mi = 0; mi < 4; mi++)
            #pragma unroll
            for (int ni = 0; ni < 4; ni++)
                mma16816(c[mi][ni], a[mi], bb[ni]);
    }
    __syncthreads();   // staging region is about to be reused as output stage

    // epilogue: scale by rz1*rz2, pack bf16x2, write to padded stage
    {
        uint32_t* stg = (uint32_t*)(smem + SM_STG);
        const float* rz1s = (const float*)(smem + SM_RZ1);
        const float* rz2s = (const float*)(smem + SM_RZ2);
        #pragma unroll
        for (int mi = 0; mi < 4; mi++) {
            int r0 = (wm << 6) + (mi << 4) + (lane >> 2);
            int r1 = r0 + 8;
            float z1a = rz1s[r0], z1b = rz1s[r1];
            #pragma unroll
            for (int ni = 0; ni < 4; ni++) {
                int cq = (wn << 5) + (ni << 3) + ((lane & 3) << 1);
                float rq0 = rz2s[cq], rq1 = rz2s[cq + 1];
                uint32_t u0, u1;
                float a0 = c[mi][ni][0] * z1a * rq0, a1 = c[mi][ni][1] * z1a * rq1;
                float b0 = c[mi][ni][2] * z1b * rq0, b1 = c[mi][ni][3] * z1b * rq1;
                asm("cvt.rn.bf16x2.f32 %0, %1, %2;" : "=r"(u0) : "f"(a1), "f"(a0));
                asm("cvt.rn.bf16x2.f32 %0, %1, %2;" : "=r"(u1) : "f"(b1), "f"(b0));
                stg[r0 * STG_WPR + (cq >> 1)] = u0;
                stg[r1 * STG_WPR + (cq >> 1)] = u1;
            }
        }
    }
    __syncthreads();

    // coalesced store: 128 rows x 256B
    {
        const uint32_t* stg = (const uint32_t*)(smem + SM_STG);
        #pragma unroll
        for (int it = 0; it < 8; it++) {
            int row  = it * 16 + (t >> 4);
            int colw = (t & 15) << 2;
            uint4 v = *(const uint4*)(stg + row * STG_WPR + colw);
            size_t off = ((size_t)(b << 10) + (ptile << 7) + row) << 10;
            *(uint4*)((char*)g_gc + (off + (qtile << 7) + (colw << 1)) * 2) = v;
        }
    }
}

// ---------------- gather + merged final reduction -------------------------------
__global__ void __launch_bounds__(1024, 1)
gather_kernel(const int* __restrict__ neg_idx, const float* __restrict__ img,
              float* __restrict__ out, int out_size) {
    __shared__ float4 imgt_sm[HWn];     // 16 KB
    __shared__ float  dot_sm[32][NEGn]; // 32 KB
    __shared__ float  s0w[32];
    __shared__ float  r1s[32], r2s[32];
    __shared__ float  lb[8], s0b[8], s2b[8];
    __shared__ unsigned is_last;

    const int b    = blockIdx.x;
    const int by   = blockIdx.y;
    const int t    = threadIdx.x;
    const int w    = t >> 5;
    const int lane = t & 31;

    imgt_sm[t] = make_float4(img[t], img[HWn + t], img[2 * HWn + t], 0.f);
    __syncthreads();

    const float INV_EUC   = 1.0f / sqrtf((float)(31 * 31 + 31 * 31));
    const float INV_SQRT3 = 0.57735026919f;

    float acc[8];
    #pragma unroll
    for (int r = 0; r < 8; r++) acc[r] = 0.f;
    float sim0acc = 0.f;

    const unsigned short* gcb = g_gc + ((size_t)b << 20);

    #pragma unroll 1
    for (int it = 0; it < 2; it++) {
        const int p = (by << 6) + (w << 1) + it;
        const float z1sqp = g_z1sq[(b << 10) + p];
        const float hp = (float)(p >> 5), wp = (float)(p & 31);
        const float4 ctr = imgt_sm[p];

        const int* negH = neg_idx + ((size_t)(b * 2) << 18) + (p << 8);
        const int* negW = negH + (1 << 18);

        int qn[8];
        float eucsq = 0.f, rgbsq = 0.f;
        #pragma unroll
        for (int r = 0; r < 8; r++) {
            int n  = (r << 5) + lane;
            int nh = negH[n];
            int nw = negW[n];
            int q  = (nh << 5) + nw;
            qn[r] = q;
            float dh = hp - (float)nh, dw = wp - (float)nw;
            eucsq += dh * dh; eucsq += dw * dw;
            float4 c4 = imgt_sm[q];
            float dr = ctr.x - c4.x, dg = ctr.y - c4.y, db = ctr.z - c4.z;
            rgbsq += dr * dr; rgbsq += dg * dg; rgbsq += db * db;
        }
        #pragma unroll
        for (int s = 16; s > 0; s >>= 1) {
            eucsq += __shfl_xor_sync(0xffffffffu, eucsq, s);
            rgbsq += __shfl_xor_sync(0xffffffffu, rgbsq, s);
        }
        const float weight = 0.8f * sqrtf(eucsq) * INV_EUC
                           + 0.2f * sqrtf(rgbsq) * INV_SQRT3;

        const unsigned short* grow = gcb + ((size_t)p << 10);
        #pragma unroll
        for (int r = 0; r < 8; r++) {
            float cosv = __uint_as_float((unsigned)grow[qn[r]] << 16);
            acc[r] += fminf(fabsf(cosv * weight), 1.0f);
        }
        if (lane == 0) {
            float c0 = z1sqp / fmaxf(z1sqp, 1e-8f);
            sim0acc += fminf(fabsf(c0), 1.0f);
        }
    }

    #pragma unroll
    for (int r = 0; r < 8; r++) dot_sm[w][(r << 5) + lane] = acc[r];
    if (lane == 0) s0w[w] = sim0acc;
    __syncthreads();

    if (t < NEGn) {
        float s = 0.f;
        #pragma unroll
        for (int k = 0; k < 32; k++) s += dot_sm[k][t];
        g_pn[(((b << 4) + by) << 8) + t] = s;
    }
    if (t == 0) {
        float s = 0.f;
        #pragma unroll
        for (int k = 0; k < 32; k++) s += s0w[k];
        g_s0p[(b << 4) + by] = s;
    }

    // ---- last-block final reduction: fence on ONE thread only ----
    __syncthreads();
    if (t == 0) {
        __threadfence();    // release our block's g_pn/g_s0p writes
        is_last = (atomicAdd(&g_ticket, 1u) == (unsigned)(Bn * 16 - 1));
    }
    __syncthreads();
    if (!is_last) return;
    if (t == 0) {
        __threadfence();    // acquire all blocks' writes
        g_ticket = 0;       // restore invariant for next graph replay
    }
    __syncthreads();

    {
        const int fb = t >> 7;     // 128 threads per sample
        const int j  = t & 127;

        float v1 = 0.f, v2 = 0.f;
        #pragma unroll
        for (int h = 0; h < 2; h++) {
            int n = j + (h << 7);
            float s = 0.f;
            #pragma unroll
            for (int k = 0; k < 16; k++)
                s += __ldcg(&g_pn[(((fb << 4) + k) << 8) + n]);
            float sn = s * (0.5f / 1024.0f);
            v2 += sn;
            v1 += fmaxf(log1pf(-sn), -100.0f);
        }
        #pragma unroll
        for (int s = 16; s > 0; s >>= 1) {
            v1 += __shfl_xor_sync(0xffffffffu, v1, s);
            v2 += __shfl_xor_sync(0xffffffffu, v2, s);
        }
        if ((t & 31) == 0) { r1s[t >> 5] = v1; r2s[t >> 5] = v2; }
        __syncthreads();

        if (t < 8) {
            float s1 = r1s[4 * t] + r1s[4 * t + 1] + r1s[4 * t + 2] + r1s[4 * t + 3];
            float s2 = r2s[4 * t] + r2s[4 * t + 1] + r2s[4 * t + 2] + r2s[4 * t + 3];
            float s0s = 0.f;
            #pragma unroll
            for (int k = 0; k < 16; k++) s0s += __ldcg(&g_s0p[(t << 4) + k]);
            float s0   = s0s * (1.0f / 1024.0f);
            float logp = fmaxf(logf(s0), -100.0f);
            lb[t]  = -(logp + s1) * (1.0f / 257.0f);
            s0b[t] = s0;
            s2b[t] = s2;
        }
        __syncthreads();

        if (t == 0) {
            float loss = 0.f, o1 = 0.f, o2 = 0.f;
            #pragma unroll
            for (int i = 0; i < 8; i++) { loss += lb[i]; o1 += s0b[i]; o2 += s2b[i]; }
            if (out_size > 0) out[0] = loss * 0.125f;
            if (out_size > 1) out[1] = o1 * 0.125f;
            if (out_size > 2) out[2] = o2 * (2.0f / (256.0f * 8.0f));
        }
    }
}

// ---------------- launch --------------------------------------------------------
extern "C" void kernel_launch(void* const* d_in, const int* in_sizes, int n_in,
                              void* d_out, int out_size) {
    const float* v1   = (const float*)d_in[0];
    const float* v2   = (const float*)d_in[1];
    const float* img  = (const float*)d_in[2];
    const int*   nidx = (const int*)  d_in[3];

    cudaFuncSetAttribute(gemm_kernel, cudaFuncAttributeMaxDynamicSharedMemorySize,
                         SM_GEMM_TOTAL);

    gemm_kernel<<<dim3(8, 8, 8), 256, SM_GEMM_TOTAL>>>(v1, v2);
    gather_kernel<<<dim3(Bn, 16), 1024>>>(nidx, img, (float*)d_out, out_size);
}

// round 8
// speedup vs baseline: 1.1333x; 1.1333x over previous
#include <cuda_runtime.h>
#include <math.h>
#include <stdint.h>

#define Bn   8
#define HWn  1024
#define NEGn 256

// ---------------- device scratch ----------------------------------------------
__device__ __align__(16) unsigned g_z1b[Bn * HWn * 32];   // bf16x2 pixel-major, 128B rows
__device__ __align__(16) unsigned g_z2b[Bn * HWn * 32];
__device__ float g_rz1n[Bn * HWn];
__device__ float g_rz2n[Bn * HWn];
__device__ float g_z1sq[Bn * HWn];
__device__ float g_pn [128 * NEGn];
__device__ float g_s0p[128];
__device__ unsigned g_ticket = 0;

__device__ __forceinline__ uint32_t smem_to_u32(const void* p) {
    uint32_t a;
    asm("{ .reg .u64 t; cvta.to.shared.u64 t, %1; cvt.u32.u64 %0, t; }" : "=r"(a) : "l"(p));
    return a;
}
#define SMEM_SWIZZLE_128B(o) ((o) ^ (((o) >> 3) & 0x70))

// round-to-nearest-even fp32 -> bf16-valued fp32
__device__ __forceinline__ float bf16q(float f) {
    unsigned u = __float_as_uint(f);
    u = (u + 0x7FFFu + ((u >> 16) & 1u)) & 0xFFFF0000u;
    return __uint_as_float(u);
}

__device__ __forceinline__ void ldsm_x4(uint32_t& r0, uint32_t& r1, uint32_t& r2,
                                        uint32_t& r3, uint32_t addr) {
    asm volatile("ldmatrix.sync.aligned.m8n8.x4.shared.b16 {%0,%1,%2,%3}, [%4];"
                 : "=r"(r0), "=r"(r1), "=r"(r2), "=r"(r3) : "r"(addr));
}
__device__ __forceinline__ void ldsm_x2(uint32_t& r0, uint32_t& r1, uint32_t addr) {
    asm volatile("ldmatrix.sync.aligned.m8n8.x2.shared.b16 {%0,%1}, [%2];"
                 : "=r"(r0), "=r"(r1) : "r"(addr));
}
__device__ __forceinline__ void mma16816(float* c, const uint32_t* a, const uint32_t* b) {
    asm volatile("mma.sync.aligned.m16n8k16.row.col.f32.bf16.bf16.f32 "
                 "{%0,%1,%2,%3}, {%4,%5,%6,%7}, {%8,%9}, {%0,%1,%2,%3};"
                 : "+f"(c[0]), "+f"(c[1]), "+f"(c[2]), "+f"(c[3])
                 : "r"(a[0]), "r"(a[1]), "r"(a[2]), "r"(a[3]), "r"(b[0]), "r"(b[1]));
}

// ---------------- prep: transpose to bf16 pixel-major + norms ------------------
// grid (8 qt, 8 b, 2 view), 256 threads; each block handles 128 pixels
__global__ void prep_kernel(const float* __restrict__ z1,
                            const float* __restrict__ z2) {
    __shared__ float ts[64][132];
    const int s  = blockIdx.z;
    const int b  = blockIdx.y;
    const int q0 = blockIdx.x * 128;
    const int t  = threadIdx.x;

    const float* zp = s ? z2 : z1;
    #pragma unroll
    for (int it = 0; it < 8; it++) {
        int u = it * 256 + t;
        int c = u >> 5, jq = u & 31;
        float4 v = *(const float4*)(zp + ((b * 64 + c) << 10) + q0 + jq * 4);
        float* d = &ts[c][jq * 4];
        d[0] = bf16q(v.x); d[1] = bf16q(v.y);
        d[2] = bf16q(v.z); d[3] = bf16q(v.w);
    }
    __syncthreads();

    if (t < 128) {
        float sum = 0.f;
        #pragma unroll
        for (int c = 0; c < 64; c++) { float x = ts[c][t]; sum += x * x; }
        int gi = (b << 10) + q0 + t;
        if (s == 0) { g_z1sq[gi] = sum; g_rz1n[gi] = rsqrtf(sum); }
        else        { g_rz2n[gi] = rsqrtf(sum); }
    }

    unsigned* outp = s ? g_z2b : g_z1b;
    #pragma unroll
    for (int it = 0; it < 16; it++) {
        int u = it * 256 + t;
        int px = u & 127, cp = u >> 7;
        unsigned lo = __float_as_uint(ts[2 * cp][px]) >> 16;
        unsigned hi = __float_as_uint(ts[2 * cp + 1][px]) >> 16;
        outp[(((b << 10) + q0 + px) << 5) + cp] = lo | (hi << 16);
    }
}

// ---------------- fused GEMM + gather + final -----------------------------------
// grid (16 pt, 8 b), 512 threads (16 warps). Block owns a 64-p stripe:
//   MMA phase: G[64 x 1024] bf16 cosines into SMEM (8 q-tiles, double-buffered B)
//   gather phase: weight + smem-gather + sim accumulation
//   last-block tail: final reduction
#define FS_SG    0
#define SG_PITCH 2064                       // 2048B data + 16B pad -> conflict-free
#define FS_SB0   132096
#define FS_SB1   148480
#define FS_SA    164864
#define FS_RZ1   173056
#define FS_RZ2   173312
#define FS_IMG   177408                     // float4[1024]
#define FS_DOT   193792                     // float[16][256]
#define FS_MISC  210176
#define FS_TOTAL 210688

__global__ void __launch_bounds__(512) fused_kernel(
        const int* __restrict__ neg_idx, const float* __restrict__ img,
        float* __restrict__ out, int out_size) {
    extern __shared__ char smem[];
    const uint32_t sb = smem_to_u32(smem);
    const int t = threadIdx.x, w = t >> 5, lane = t & 31;
    const int pt = blockIdx.x, b = blockIdx.y;
    const int wm = w >> 3, wn = w & 7;          // 2x8 warp grid; warp tile 32p x 16q

    float*  rz1s = (float*)(smem + FS_RZ1);
    float*  rz2s = (float*)(smem + FS_RZ2);
    float4* imgs = (float4*)(smem + FS_IMG);
    float*  sdot = (float*)(smem + FS_DOT);
    float*  s0w  = (float*)(smem + FS_MISC);            // 16
    float*  r1s  = (float*)(smem + FS_MISC + 64);       // 16
    float*  r2s  = (float*)(smem + FS_MISC + 128);      // 16
    float*  lb   = (float*)(smem + FS_MISC + 192);      // 8
    float*  s0b  = (float*)(smem + FS_MISC + 224);      // 8
    float*  s2b  = (float*)(smem + FS_MISC + 256);      // 8
    unsigned* is_last = (unsigned*)(smem + FS_MISC + 288);

    // ---- prolog: A tile, first B tile, norms, img table, L2 prefetch ----
    {
        const uint4* srcA = (const uint4*)g_z1b + (((size_t)(b << 10) + (pt << 6)) << 3);
        int row = t >> 3, ub = t & 7;   // 512 = 64 rows x 8
        *(uint4*)(smem + FS_SA + SMEM_SWIZZLE_128B((uint32_t)(row * 128 + ub * 16))) = srcA[t];

        const uint4* srcB = (const uint4*)g_z2b + ((size_t)(b << 10) << 3);
        #pragma unroll
        for (int k = 0; k < 2; k++) {
            int u = k * 512 + t;
            int r2 = u >> 3, u2 = u & 7;
            *(uint4*)(smem + FS_SB0 + SMEM_SWIZZLE_128B((uint32_t)(r2 * 128 + u2 * 16))) = srcB[u];
        }
        if (t < 64) rz1s[t] = g_rz1n[(b << 10) + (pt << 6) + t];
        #pragma unroll
        for (int k = 0; k < 2; k++) {
            int i = k * 512 + t;
            rz2s[i] = g_rz2n[(b << 10) + i];
            imgs[i] = make_float4(img[i], img[HWn + i], img[2 * HWn + i], 0.f);
        }
        // L2-prefetch this block's neg_idx slice (64 p x 256 x 2 ints = 128KB)
        const char* nh = (const char*)(neg_idx + ((size_t)(b * 2) << 18) + ((pt << 6) << 8));
        asm volatile("prefetch.global.L2 [%0];" :: "l"(nh + t * 128));
        asm volatile("prefetch.global.L2 [%0];" :: "l"(nh + (1 << 20) + t * 128));
    }
    __syncthreads();

    // ---- hoist A fragments (constant across q-tiles) ----
    uint32_t af[4][2][4];
    #pragma unroll
    for (int ks = 0; ks < 4; ks++)
        #pragma unroll
        for (int mi = 0; mi < 2; mi++) {
            int row  = (wm << 5) + (mi << 4) + (lane & 15);
            int half = lane >> 4;
            uint32_t off = SMEM_SWIZZLE_128B((uint32_t)(row * 128 + ks * 32 + half * 16));
            ldsm_x4(af[ks][mi][0], af[ks][mi][1], af[ks][mi][2], af[ks][mi][3],
                    sb + FS_SA + off);
        }

    // ---- MMA mainloop over 8 q-tiles ----
    #pragma unroll 1
    for (int qt = 0; qt < 8; qt++) {
        const int cur = qt & 1;
        const uint32_t sbB = sb + (cur ? FS_SB1 : FS_SB0);

        if (qt < 7) {  // prefetch next B tile into the other buffer
            const int nxt = cur ^ 1;
            const uint4* srcB = (const uint4*)g_z2b +
                                (((size_t)(b << 10) + ((qt + 1) << 7)) << 3);
            #pragma unroll
            for (int k = 0; k < 2; k++) {
                int u = k * 512 + t;
                int r2 = u >> 3, u2 = u & 7;
                *(uint4*)(smem + (nxt ? FS_SB1 : FS_SB0) +
                          SMEM_SWIZZLE_128B((uint32_t)(r2 * 128 + u2 * 16))) = srcB[u];
            }
        }

        float c[2][2][4];
        #pragma unroll
        for (int mi = 0; mi < 2; mi++)
            #pragma unroll
            for (int ni = 0; ni < 2; ni++)
                #pragma unroll
                for (int r = 0; r < 4; r++) c[mi][ni][r] = 0.f;

        #pragma unroll
        for (int ks = 0; ks < 4; ks++) {
            uint32_t bb[2][2];
            #pragma unroll
            for (int ni = 0; ni < 2; ni++) {
                int row  = (wn << 4) + (ni << 3) + (lane & 7);
                int half = (lane >> 3) & 1;
                uint32_t off = SMEM_SWIZZLE_128B((uint32_t)(row * 128 + ks * 32 + half * 16));
                ldsm_x2(bb[ni][0], bb[ni][1], sbB + off);
            }
            #pragma unroll
            for (int mi = 0; mi < 2; mi++)
                #pragma unroll
                for (int ni = 0; ni < 2; ni++)
                    mma16816(c[mi][ni], af[ks][mi], bb[ni]);
        }

        // epilogue: scale -> bf16x2 -> STS into SG (conflict-free via pitch 2064)
        #pragma unroll
        for (int mi = 0; mi < 2; mi++) {
            int r0 = (wm << 5) + (mi << 4) + (lane >> 2);
            int r1 = r0 + 8;
            float z1a = rz1s[r0], z1b = rz1s[r1];
            #pragma unroll
            for (int ni = 0; ni < 2; ni++) {
                int cq = (wn << 4) + (ni << 3) + ((lane & 3) << 1);
                int gq = (qt << 7) + cq;
                float rq0 = rz2s[gq], rq1 = rz2s[gq + 1];
                uint32_t u0, u1;
                float a0 = c[mi][ni][0] * z1a * rq0, a1 = c[mi][ni][1] * z1a * rq1;
                float b0 = c[mi][ni][2] * z1b * rq0, b1 = c[mi][ni][3] * z1b * rq1;
                asm("cvt.rn.bf16x2.f32 %0, %1, %2;" : "=r"(u0) : "f"(a1), "f"(a0));
                asm("cvt.rn.bf16x2.f32 %0, %1, %2;" : "=r"(u1) : "f"(b1), "f"(b0));
                *(uint32_t*)(smem + FS_SG + r0 * SG_PITCH + gq * 2) = u0;
                *(uint32_t*)(smem + FS_SG + r1 * SG_PITCH + gq * 2) = u1;
            }
        }
        __syncthreads();
    }

    // ---- gather phase: 16 warps x 4 p = 64 p, gathers hit SMEM ----
    const float INV_EUC   = 1.0f / sqrtf((float)(31 * 31 + 31 * 31));
    const float INV_SQRT3 = 0.57735026919f;

    float acc[8];
    #pragma unroll
    for (int r = 0; r < 8; r++) acc[r] = 0.f;
    float sim0acc = 0.f;

    #pragma unroll 1
    for (int it = 0; it < 4; it++) {
        const int pl = (w << 2) + it;            // local p 0..63
        const int p  = (pt << 6) + pl;
        const float z1sqp = g_z1sq[(b << 10) + p];
        const float hp = (float)(p >> 5), wp = (float)(p & 31);
        const float4 ctr = imgs[p];

        const int* negH = neg_idx + ((size_t)(b * 2) << 18) + (p << 8);
        const int* negW = negH + (1 << 18);

        int qn[8];
        float eucsq = 0.f, rgbsq = 0.f;
        #pragma unroll
        for (int r = 0; r < 8; r++) {
            int n  = (r << 5) + lane;
            int nh = negH[n];
            int nw = negW[n];
            int q  = (nh << 5) + nw;
            qn[r] = q;
            float dh = hp - (float)nh, dw = wp - (float)nw;
            eucsq += dh * dh; eucsq += dw * dw;
            float4 c4 = imgs[q];
            float dr = ctr.x - c4.x, dg = ctr.y - c4.y, db = ctr.z - c4.z;
            rgbsq += dr * dr; rgbsq += dg * dg; rgbsq += db * db;
        }
        #pragma unroll
        for (int s = 16; s > 0; s >>= 1) {
            eucsq += __shfl_xor_sync(0xffffffffu, eucsq, s);
            rgbsq += __shfl_xor_sync(0xffffffffu, rgbsq, s);
        }
        const float weight = 0.8f * sqrtf(eucsq) * INV_EUC
                           + 0.2f * sqrtf(rgbsq) * INV_SQRT3;

        const unsigned short* grow = (const unsigned short*)(smem + FS_SG + pl * SG_PITCH);
        #pragma unroll
        for (int r = 0; r < 8; r++) {
            float cosv = __uint_as_float((unsigned)grow[qn[r]] << 16);
            acc[r] += fminf(fabsf(cosv * weight), 1.0f);
        }
        if (lane == 0) {
            float c0 = z1sqp / fmaxf(z1sqp, 1e-8f);
            sim0acc += fminf(fabsf(c0), 1.0f);
        }
    }

    #pragma unroll
    for (int r = 0; r < 8; r++) sdot[w * 256 + (r << 5) + lane] = acc[r];
    if (lane == 0) s0w[w] = sim0acc;
    __syncthreads();

    if (t < NEGn) {
        float s = 0.f;
        #pragma unroll
        for (int k = 0; k < 16; k++) s += sdot[k * 256 + t];
        g_pn[(((b << 4) + pt) << 8) + t] = s;
    }
    if (t == 0) {
        float s = 0.f;
        #pragma unroll
        for (int k = 0; k < 16; k++) s += s0w[k];
        g_s0p[(b << 4) + pt] = s;
    }

    // ---- last-block final reduction: fence on ONE thread only ----
    __syncthreads();
    if (t == 0) {
        __threadfence();    // release this block's g_pn/g_s0p writes
        *is_last = (atomicAdd(&g_ticket, 1u) == 127u);
    }
    __syncthreads();
    if (!*is_last) return;
    if (t == 0) {
        __threadfence();    // acquire all blocks' writes
        g_ticket = 0;       // restore invariant for next graph replay
    }
    __syncthreads();

    {
        const int fb = t >> 6;     // 64 threads per sample (8 samples x 64 = 512)
        const int j  = t & 63;

        float v1 = 0.f, v2 = 0.f;
        #pragma unroll
        for (int h = 0; h < 4; h++) {
            int n = j + (h << 6);
            float s = 0.f;
            #pragma unroll
            for (int k = 0; k < 16; k++)
                s += __ldcg(&g_pn[(((fb << 4) + k) << 8) + n]);
            float sn = s * (0.5f / 1024.0f);
            v2 += sn;
            v1 += fmaxf(log1pf(-sn), -100.0f);
        }
        #pragma unroll
        for (int s = 16; s > 0; s >>= 1) {
            v1 += __shfl_xor_sync(0xffffffffu, v1, s);
            v2 += __shfl_xor_sync(0xffffffffu, v2, s);
        }
        if (lane == 0) { r1s[w] = v1; r2s[w] = v2; }
        __syncthreads();

        if (t < 8) {   // one thread per sample: warps 2t and 2t+1
            float s1 = r1s[2 * t] + r1s[2 * t + 1];
            float s2 = r2s[2 * t] + r2s[2 * t + 1];
            float s0s = 0.f;
            #pragma unroll
            for (int k = 0; k < 16; k++) s0s += __ldcg(&g_s0p[(t << 4) + k]);
            float s0   = s0s * (1.0f / 1024.0f);
            float logp = fmaxf(logf(s0), -100.0f);
            lb[t]  = -(logp + s1) * (1.0f / 257.0f);
            s0b[t] = s0;
            s2b[t] = s2;
        }
        __syncthreads();

        if (t == 0) {
            float loss = 0.f, o1 = 0.f, o2 = 0.f;
            #pragma unroll
            for (int i = 0; i < 8; i++) { loss += lb[i]; o1 += s0b[i]; o2 += s2b[i]; }
            if (out_size > 0) out[0] = loss * 0.125f;
            if (out_size > 1) out[1] = o1 * 0.125f;
            if (out_size > 2) out[2] = o2 * (2.0f / (256.0f * 8.0f));
        }
    }
}

// ---------------- launch --------------------------------------------------------
extern "C" void kernel_launch(void* const* d_in, const int* in_sizes, int n_in,
                              void* d_out, int out_size) {
    const float* v1   = (const float*)d_in[0];
    const float* v2   = (const float*)d_in[1];
    const float* img  = (const float*)d_in[2];
    const int*   nidx = (const int*)  d_in[3];

    cudaFuncSetAttribute(fused_kernel, cudaFuncAttributeMaxDynamicSharedMemorySize,
                         FS_TOTAL);

    prep_kernel<<<dim3(8, 8, 2), 256>>>(v1, v2);
    fused_kernel<<<dim3(16, 8), 512, FS_TOTAL>>>(nidx, img, (float*)d_out, out_size);
}

// round 9
// speedup vs baseline: 1.2352x; 1.0900x over previous
#include <cuda_runtime.h>
#include <math.h>
#include <stdint.h>

#define Bn   8
#define HWn  1024
#define NEGn 256

// ---------------- device scratch ----------------------------------------------
__device__ __align__(16) unsigned g_z1b[Bn * HWn * 32];   // bf16x2 pixel-major, 128B rows
__device__ __align__(16) unsigned g_z2b[Bn * HWn * 32];
__device__ float g_rz1n[Bn * HWn];
__device__ float g_rz2n[Bn * HWn];
__device__ float g_z1sq[Bn * HWn];
__device__ float g_pn [128 * NEGn];
__device__ float g_s0p[128];
__device__ unsigned g_ticket = 0;

__device__ __forceinline__ uint32_t smem_to_u32(const void* p) {
    uint32_t a;
    asm("{ .reg .u64 t; cvta.to.shared.u64 t, %1; cvt.u32.u64 %0, t; }" : "=r"(a) : "l"(p));
    return a;
}
#define SMEM_SWIZZLE_128B(o) ((o) ^ (((o) >> 3) & 0x70))
#define CP_ASYNC16(dst_u32, src) \
    asm volatile("cp.async.cg.shared.global [%0], [%1], 16;" :: "r"(dst_u32), "l"(src))
#define CP_COMMIT() asm volatile("cp.async.commit_group;" ::: "memory")
#define CP_WAIT0()  asm volatile("cp.async.wait_group 0;" ::: "memory")

// round-to-nearest-even fp32 -> bf16-valued fp32
__device__ __forceinline__ float bf16q(float f) {
    unsigned u = __float_as_uint(f);
    u = (u + 0x7FFFu + ((u >> 16) & 1u)) & 0xFFFF0000u;
    return __uint_as_float(u);
}

__device__ __forceinline__ void ldsm_x4(uint32_t& r0, uint32_t& r1, uint32_t& r2,
                                        uint32_t& r3, uint32_t addr) {
    asm volatile("ldmatrix.sync.aligned.m8n8.x4.shared.b16 {%0,%1,%2,%3}, [%4];"
                 : "=r"(r0), "=r"(r1), "=r"(r2), "=r"(r3) : "r"(addr));
}
__device__ __forceinline__ void ldsm_x2(uint32_t& r0, uint32_t& r1, uint32_t addr) {
    asm volatile("ldmatrix.sync.aligned.m8n8.x2.shared.b16 {%0,%1}, [%2];"
                 : "=r"(r0), "=r"(r1) : "r"(addr));
}
__device__ __forceinline__ void mma16816(float* c, const uint32_t* a, const uint32_t* b) {
    asm volatile("mma.sync.aligned.m16n8k16.row.col.f32.bf16.bf16.f32 "
                 "{%0,%1,%2,%3}, {%4,%5,%6,%7}, {%8,%9}, {%0,%1,%2,%3};"
                 : "+f"(c[0]), "+f"(c[1]), "+f"(c[2]), "+f"(c[3])
                 : "r"(a[0]), "r"(a[1]), "r"(a[2]), "r"(a[3]), "r"(b[0]), "r"(b[1]));
}

// ---------------- prep: transpose to bf16 pixel-major + norms ------------------
__global__ void prep_kernel(const float* __restrict__ z1,
                            const float* __restrict__ z2) {
    __shared__ float ts[64][132];
    const int s  = blockIdx.z;
    const int b  = blockIdx.y;
    const int q0 = blockIdx.x * 128;
    const int t  = threadIdx.x;

    const float* zp = s ? z2 : z1;
    #pragma unroll
    for (int it = 0; it < 8; it++) {
        int u = it * 256 + t;
        int c = u >> 5, jq = u & 31;
        float4 v = *(const float4*)(zp + ((b * 64 + c) << 10) + q0 + jq * 4);
        float* d = &ts[c][jq * 4];
        d[0] = bf16q(v.x); d[1] = bf16q(v.y);
        d[2] = bf16q(v.z); d[3] = bf16q(v.w);
    }
    __syncthreads();

    if (t < 128) {
        float sum = 0.f;
        #pragma unroll
        for (int c = 0; c < 64; c++) { float x = ts[c][t]; sum += x * x; }
        int gi = (b << 10) + q0 + t;
        if (s == 0) { g_z1sq[gi] = sum; g_rz1n[gi] = rsqrtf(sum); }
        else        { g_rz2n[gi] = rsqrtf(sum); }
    }

    unsigned* outp = s ? g_z2b : g_z1b;
    #pragma unroll
    for (int it = 0; it < 16; it++) {
        int u = it * 256 + t;
        int px = u & 127, cp = u >> 7;
        unsigned lo = __float_as_uint(ts[2 * cp][px]) >> 16;
        unsigned hi = __float_as_uint(ts[2 * cp + 1][px]) >> 16;
        outp[(((b << 10) + q0 + px) << 5) + cp] = lo | (hi << 16);
    }
}

// ---------------- fused GEMM + gather + final -----------------------------------
#define FS_SG    0
#define SG_PITCH 2064
#define FS_SB0   132096
#define FS_SB1   148480
#define FS_SA    164864
#define FS_RZ1   173056
#define FS_RZ2   173312
#define FS_IMG   177408
#define FS_DOT   193792
#define FS_MISC  210176
#define FS_TOTAL 210688

__global__ void __launch_bounds__(512) fused_kernel(
        const int* __restrict__ neg_idx, const float* __restrict__ img,
        float* __restrict__ out, int out_size) {
    extern __shared__ char smem[];
    const uint32_t sb = smem_to_u32(smem);
    const int t = threadIdx.x, w = t >> 5, lane = t & 31;
    const int pt = blockIdx.x, b = blockIdx.y;
    const int wm = w >> 3, wn = w & 7;

    float*  rz1s = (float*)(smem + FS_RZ1);
    float*  rz2s = (float*)(smem + FS_RZ2);
    float4* imgs = (float4*)(smem + FS_IMG);
    float*  sdot = (float*)(smem + FS_DOT);
    float*  s0w  = (float*)(smem + FS_MISC);
    float*  r1s  = (float*)(smem + FS_MISC + 64);
    float*  r2s  = (float*)(smem + FS_MISC + 128);
    float*  lb   = (float*)(smem + FS_MISC + 192);
    float*  s0b  = (float*)(smem + FS_MISC + 224);
    float*  s2b  = (float*)(smem + FS_MISC + 256);
    unsigned* is_last = (unsigned*)(smem + FS_MISC + 288);

    // ---- prolog: A + B0 via cp.async, norms, img table, L2 prefetch ----
    {
        const uint4* srcA = (const uint4*)g_z1b + (((size_t)(b << 10) + (pt << 6)) << 3);
        int row = t >> 3, ub = t & 7;
        CP_ASYNC16(sb + FS_SA + SMEM_SWIZZLE_128B((uint32_t)(row * 128 + ub * 16)),
                   srcA + t);

        const uint4* srcB = (const uint4*)g_z2b + ((size_t)(b << 10) << 3);
        #pragma unroll
        for (int k = 0; k < 2; k++) {
            int u = k * 512 + t;
            int r2 = u >> 3, u2 = u & 7;
            CP_ASYNC16(sb + FS_SB0 + SMEM_SWIZZLE_128B((uint32_t)(r2 * 128 + u2 * 16)),
                       srcB + u);
        }
        CP_COMMIT();

        if (t < 64) rz1s[t] = g_rz1n[(b << 10) + (pt << 6) + t];
        #pragma unroll
        for (int k = 0; k < 2; k++) {
            int i = k * 512 + t;
            rz2s[i] = g_rz2n[(b << 10) + i];
            imgs[i] = make_float4(img[i], img[HWn + i], img[2 * HWn + i], 0.f);
        }
        // L2-prefetch this block's neg_idx slice
        const char* nh = (const char*)(neg_idx + ((size_t)(b * 2) << 18) + ((pt << 6) << 8));
        asm volatile("prefetch.global.L2 [%0];" :: "l"(nh + t * 128));
        asm volatile("prefetch.global.L2 [%0];" :: "l"(nh + (1 << 20) + t * 128));
        CP_WAIT0();
    }
    __syncthreads();

    // ---- hoist A fragments ----
    uint32_t af[4][2][4];
    #pragma unroll
    for (int ks = 0; ks < 4; ks++)
        #pragma unroll
        for (int mi = 0; mi < 2; mi++) {
            int row  = (wm << 5) + (mi << 4) + (lane & 15);
            int half = lane >> 4;
            uint32_t off = SMEM_SWIZZLE_128B((uint32_t)(row * 128 + ks * 32 + half * 16));
            ldsm_x4(af[ks][mi][0], af[ks][mi][1], af[ks][mi][2], af[ks][mi][3],
                    sb + FS_SA + off);
        }

    // ---- MMA mainloop over 8 q-tiles (cp.async double-buffered B) ----
    #pragma unroll 1
    for (int qt = 0; qt < 8; qt++) {
        const int cur = qt & 1;
        const uint32_t sbB = sb + (cur ? FS_SB1 : FS_SB0);

        if (qt < 7) {
            const uint32_t dstB = sb + ((cur ^ 1) ? FS_SB1 : FS_SB0);
            const uint4* srcB = (const uint4*)g_z2b +
                                (((size_t)(b << 10) + ((qt + 1) << 7)) << 3);
            #pragma unroll
            for (int k = 0; k < 2; k++) {
                int u = k * 512 + t;
                int r2 = u >> 3, u2 = u & 7;
                CP_ASYNC16(dstB + SMEM_SWIZZLE_128B((uint32_t)(r2 * 128 + u2 * 16)),
                           srcB + u);
            }
        }
        CP_COMMIT();

        float c[2][2][4];
        #pragma unroll
        for (int mi = 0; mi < 2; mi++)
            #pragma unroll
            for (int ni = 0; ni < 2; ni++)
                #pragma unroll
                for (int r = 0; r < 4; r++) c[mi][ni][r] = 0.f;

        #pragma unroll
        for (int ks = 0; ks < 4; ks++) {
            uint32_t bb[2][2];
            #pragma unroll
            for (int ni = 0; ni < 2; ni++) {
                int row  = (wn << 4) + (ni << 3) + (lane & 7);
                int half = (lane >> 3) & 1;
                uint32_t off = SMEM_SWIZZLE_128B((uint32_t)(row * 128 + ks * 32 + half * 16));
                ldsm_x2(bb[ni][0], bb[ni][1], sbB + off);
            }
            #pragma unroll
            for (int mi = 0; mi < 2; mi++)
                #pragma unroll
                for (int ni = 0; ni < 2; ni++)
                    mma16816(c[mi][ni], af[ks][mi], bb[ni]);
        }

        // epilogue: scale -> bf16x2 -> STS into SG
        #pragma unroll
        for (int mi = 0; mi < 2; mi++) {
            int r0 = (wm << 5) + (mi << 4) + (lane >> 2);
            int r1 = r0 + 8;
            float z1a = rz1s[r0], z1b = rz1s[r1];
            #pragma unroll
            for (int ni = 0; ni < 2; ni++) {
                int cq = (wn << 4) + (ni << 3) + ((lane & 3) << 1);
                int gq = (qt << 7) + cq;
                float rq0 = rz2s[gq], rq1 = rz2s[gq + 1];
                uint32_t u0, u1;
                float a0 = c[mi][ni][0] * z1a * rq0, a1 = c[mi][ni][1] * z1a * rq1;
                float b0 = c[mi][ni][2] * z1b * rq0, b1 = c[mi][ni][3] * z1b * rq1;
                asm("cvt.rn.bf16x2.f32 %0, %1, %2;" : "=r"(u0) : "f"(a1), "f"(a0));
                asm("cvt.rn.bf16x2.f32 %0, %1, %2;" : "=r"(u1) : "f"(b1), "f"(b0));
                *(uint32_t*)(smem + FS_SG + r0 * SG_PITCH + gq * 2) = u0;
                *(uint32_t*)(smem + FS_SG + r1 * SG_PITCH + gq * 2) = u1;
            }
        }
        CP_WAIT0();
        __syncthreads();
    }

    // ---- gather phase: software-pipelined neg loads ----
    const float INV_EUC   = 1.0f / sqrtf((float)(31 * 31 + 31 * 31));
    const float INV_SQRT3 = 0.57735026919f;

    float acc[8];
    #pragma unroll
    for (int r = 0; r < 8; r++) acc[r] = 0.f;
    float sim0acc = 0.f;

    const int* negHb = neg_idx + ((size_t)(b * 2) << 18);
    const int* negWb = negHb + (1 << 18);
    const int p0 = (pt << 6) + (w << 2);

    // prefetch it=0 q-indices
    int qx[8];
    {
        const int* nH = negHb + (p0 << 8);
        const int* nW = negWb + (p0 << 8);
        #pragma unroll
        for (int r = 0; r < 8; r++) {
            int n = (r << 5) + lane;
            qx[r] = (nH[n] << 5) + nW[n];
        }
    }

    #pragma unroll
    for (int it = 0; it < 4; it++) {
        int qc[8];
        #pragma unroll
        for (int r = 0; r < 8; r++) qc[r] = qx[r];

        if (it < 3) {   // prefetch next p's q-indices (overlaps compute below)
            const int* nH = negHb + ((p0 + it + 1) << 8);
            const int* nW = negWb + ((p0 + it + 1) << 8);
            #pragma unroll
            for (int r = 0; r < 8; r++) {
                int n = (r << 5) + lane;
                qx[r] = (nH[n] << 5) + nW[n];
            }
        }

        const int pl = (w << 2) + it;
        const int p  = p0 + it;
        const float z1sqp = g_z1sq[(b << 10) + p];
        const float hp = (float)(p >> 5), wp = (float)(p & 31);
        const float4 ctr = imgs[p];

        float eucsq = 0.f, rgbsq = 0.f;
        #pragma unroll
        for (int r = 0; r < 8; r++) {
            int q  = qc[r];
            int nh = q >> 5, nw = q & 31;
            float dh = hp - (float)nh, dw = wp - (float)nw;
            eucsq += dh * dh; eucsq += dw * dw;
            float4 c4 = imgs[q];
            float dr = ctr.x - c4.x, dg = ctr.y - c4.y, db = ctr.z - c4.z;
            rgbsq += dr * dr; rgbsq += dg * dg; rgbsq += db * db;
        }
        #pragma unroll
        for (int s = 16; s > 0; s >>= 1) {
            eucsq += __shfl_xor_sync(0xffffffffu, eucsq, s);
            rgbsq += __shfl_xor_sync(0xffffffffu, rgbsq, s);
        }
        const float weight = 0.8f * sqrtf(eucsq) * INV_EUC
                           + 0.2f * sqrtf(rgbsq) * INV_SQRT3;

        const unsigned short* grow = (const unsigned short*)(smem + FS_SG + pl * SG_PITCH);
        #pragma unroll
        for (int r = 0; r < 8; r++) {
            float cosv = __uint_as_float((unsigned)grow[qc[r]] << 16);
            acc[r] += fminf(fabsf(cosv * weight), 1.0f);
        }
        if (lane == 0) {
            float c0 = z1sqp / fmaxf(z1sqp, 1e-8f);
            sim0acc += fminf(fabsf(c0), 1.0f);
        }
    }

    #pragma unroll
    for (int r = 0; r < 8; r++) sdot[w * 256 + (r << 5) + lane] = acc[r];
    if (lane == 0) s0w[w] = sim0acc;
    __syncthreads();

    if (t < NEGn) {
        float s = 0.f;
        #pragma unroll
        for (int k = 0; k < 16; k++) s += sdot[k * 256 + t];
        g_pn[(((b << 4) + pt) << 8) + t] = s;
    }
    if (t == 0) {
        float s = 0.f;
        #pragma unroll
        for (int k = 0; k < 16; k++) s += s0w[k];
        g_s0p[(b << 4) + pt] = s;
    }

    // ---- last-block final reduction: fence on ONE thread only ----
    __syncthreads();
    if (t == 0) {
        __threadfence();
        *is_last = (atomicAdd(&g_ticket, 1u) == 127u);
    }
    __syncthreads();
    if (!*is_last) return;
    if (t == 0) {
        __threadfence();
        g_ticket = 0;
    }
    __syncthreads();

    {
        const int fb = t >> 6;
        const int j  = t & 63;

        float v1 = 0.f, v2 = 0.f;
        #pragma unroll
        for (int h = 0; h < 4; h++) {
            int n = j + (h << 6);
            float s = 0.f;
            #pragma unroll
            for (int k = 0; k < 16; k++)
                s += __ldcg(&g_pn[(((fb << 4) + k) << 8) + n]);
            float sn = s * (0.5f / 1024.0f);
            v2 += sn;
            v1 += fmaxf(log1pf(-sn), -100.0f);
        }
        #pragma unroll
        for (int s = 16; s > 0; s >>= 1) {
            v1 += __shfl_xor_sync(0xffffffffu, v1, s);
            v2 += __shfl_xor_sync(0xffffffffu, v2, s);
        }
        if (lane == 0) { r1s[w] = v1; r2s[w] = v2; }
        __syncthreads();

        if (t < 8) {
            float s1 = r1s[2 * t] + r1s[2 * t + 1];
            float s2 = r2s[2 * t] + r2s[2 * t + 1];
            float s0s = 0.f;
            #pragma unroll
            for (int k = 0; k < 16; k++) s0s += __ldcg(&g_s0p[(t << 4) + k]);
            float s0   = s0s * (1.0f / 1024.0f);
            float logp = fmaxf(logf(s0), -100.0f);
            lb[t]  = -(logp + s1) * (1.0f / 257.0f);
            s0b[t] = s0;
            s2b[t] = s2;
        }
        __syncthreads();

        if (t == 0) {
            float loss = 0.f, o1 = 0.f, o2 = 0.f;
            #pragma unroll
            for (int i = 0; i < 8; i++) { loss += lb[i]; o1 += s0b[i]; o2 += s2b[i]; }
            if (out_size > 0) out[0] = loss * 0.125f;
            if (out_size > 1) out[1] = o1 * 0.125f;
            if (out_size > 2) out[2] = o2 * (2.0f / (256.0f * 8.0f));
        }
    }
}

// ---------------- launch --------------------------------------------------------
extern "C" void kernel_launch(void* const* d_in, const int* in_sizes, int n_in,
                              void* d_out, int out_size) {
    const float* v1   = (const float*)d_in[0];
    const float* v2   = (const float*)d_in[1];
    const float* img  = (const float*)d_in[2];
    const int*   nidx = (const int*)  d_in[3];

    cudaFuncSetAttribute(fused_kernel, cudaFuncAttributeMaxDynamicSharedMemorySize,
                         FS_TOTAL);

    prep_kernel<<<dim3(8, 8, 2), 256>>>(v1, v2);
    fused_kernel<<<dim3(16, 8), 512, FS_TOTAL>>>(nidx, img, (float*)d_out, out_size);
}